// round 1
// baseline (speedup 1.0000x reference)
#include <cuda_runtime.h>

// ---------------- scratch (static device globals; no allocs allowed) ----------------
__device__ float g_Kh [16*4*1024*240];   // [B,H,N,240]
__device__ float g_Vh [16*4*1024*240];   // [B,H,N,240]
__device__ float g_Q  [16*4*1024*240];   // [B,H,N,240] (4 scales packed at col offsets 0/16/48/112)
__device__ float g_S  [16*4*240*240];    // [B,H,240,240] scores -> probs (in place)
__device__ float g_ctx[16*1024*960];     // per-scale ctx in [B,N,c] layout, concatenated

// head-channel regrouping of emb_all: head h, local dim d -> emb_all channel
__device__ __forceinline__ int head_map(int d, int h) {
    if (d < 16)  return h*16  + d;
    if (d < 48)  return 64  + h*32  + (d-16);
    if (d < 112) return 192 + h*64  + (d-48);
    return 448 + h*128 + (d-112);
}

// ---------------- generic tiled GEMM ----------------
// NT (TN=false): C[m,n] = sum_k A[m*lda+k] * B[n*ldb+k]
// TN (TN=true) : C[m,n] = sum_k A[k*lda+m] * B[k*ldb+n]
// GATHER: A column index remapped via head_map (K/V projection from emb_all)
// CMODE 0: plain store C[m*ldc+n]; CMODE 1: ctx scatter (transpose(0,3,2,1) interleave)
// blockIdx.z -> (b = z>>2, h = z&3); per-b / per-h strides passed explicitly.
template<bool TN, bool GATHER, int CMODE>
__global__ __launch_bounds__(256) void gemm_k(
    const float* __restrict__ A, long a_bs, long a_hs, int lda,
    const float* __restrict__ B, long b_bs, long b_hs, int ldb,
    float* __restrict__ C, long c_bs, long c_hs, int ldc,
    int M, int Nn, int Kk)
{
    __shared__ float As[16][68];
    __shared__ float Bs[16][68];

    const int z = blockIdx.z;
    const int b = z >> 2, h = z & 3;
    A += (long)b*a_bs + (long)h*a_hs;
    B += (long)b*b_bs + (long)h*b_hs;
    if (CMODE == 0) C += (long)b*c_bs + (long)h*c_hs;

    const int tid = threadIdx.x;
    const int tx = tid & 15, ty = tid >> 4;
    const int m0 = blockIdx.x * 64, n0 = blockIdx.y * 64;

    float acc[4][4];
    #pragma unroll
    for (int i = 0; i < 4; i++)
        #pragma unroll
        for (int j = 0; j < 4; j++) acc[i][j] = 0.f;

    for (int k0 = 0; k0 < Kk; k0 += 16) {
        if (!TN) {
            // A tile [64 m][16 k], transposed into As[k][m]
            int r = tid >> 2, kq = (tid & 3) * 4;
            int m = m0 + r;
            float4 v = make_float4(0.f, 0.f, 0.f, 0.f);
            if (m < M) {
                int k = k0 + kq;
                const float* p = GATHER ? (A + (long)m*lda + head_map(k, h))
                                        : (A + (long)m*lda + k);
                v = *(const float4*)p;
            }
            As[kq+0][r] = v.x; As[kq+1][r] = v.y; As[kq+2][r] = v.z; As[kq+3][r] = v.w;

            int n = n0 + r;
            float4 w = make_float4(0.f, 0.f, 0.f, 0.f);
            if (n < Nn) w = *(const float4*)(B + (long)n*ldb + k0 + kq);
            Bs[kq+0][r] = w.x; Bs[kq+1][r] = w.y; Bs[kq+2][r] = w.z; Bs[kq+3][r] = w.w;
        } else {
            // A tile [16 k][64 m] loaded directly
            int kr = tid >> 4, q = (tid & 15) * 4;
            float4 v = make_float4(0.f, 0.f, 0.f, 0.f);
            if (m0 + q < M) v = *(const float4*)(A + (long)(k0+kr)*lda + m0 + q);
            *(float4*)&As[kr][q] = v;
            float4 w = make_float4(0.f, 0.f, 0.f, 0.f);
            if (n0 + q < Nn) w = *(const float4*)(B + (long)(k0+kr)*ldb + n0 + q);
            *(float4*)&Bs[kr][q] = w;
        }
        __syncthreads();

        #pragma unroll
        for (int k = 0; k < 16; k++) {
            float4 a4 = *(const float4*)&As[k][ty*4];
            float4 b4 = *(const float4*)&Bs[k][tx*4];
            float a[4] = {a4.x, a4.y, a4.z, a4.w};
            float bb[4] = {b4.x, b4.y, b4.z, b4.w};
            #pragma unroll
            for (int i = 0; i < 4; i++)
                #pragma unroll
                for (int j = 0; j < 4; j++)
                    acc[i][j] = fmaf(a[i], bb[j], acc[i][j]);
        }
        __syncthreads();
    }

    #pragma unroll
    for (int i = 0; i < 4; i++) {
        int m = m0 + ty*4 + i;
        if (m >= M) continue;
        #pragma unroll
        for (int j = 0; j < 4; j++) {
            int n = n0 + tx*4 + j;
            if (n >= Nn) continue;
            if (CMODE == 0) {
                C[(long)m*ldc + n] = acc[i][j];
            } else {
                // m is row in stacked 240-dim; map to (scale, local dim)
                int s, doff;
                if      (m < 16)  { s = 0; doff = m; }
                else if (m < 48)  { s = 1; doff = m - 16; }
                else if (m < 112) { s = 2; doff = m - 48; }
                else              { s = 3; doff = m - 112; }
                const long ctxoff[4] = {0, 16384L*64, 16384L*192, 16384L*448};
                const int  chc[4]    = {64, 128, 256, 512};
                // ctx channel = doff*H + h; row = (b*1024 + n)
                C[ctxoff[s] + ((long)(b*1024 + n))*chc[s] + doff*4 + h] = acc[i][j];
            }
        }
    }
}

// ---------------- instance-norm (per b,h,scale over [d,240]) + row softmax ----------------
__global__ __launch_bounds__(256) void norm_softmax_k(float* __restrict__ S)
{
    const int roff[4] = {0, 16, 48, 112};
    const int dsz[4]  = {16, 32, 64, 128};
    const int s  = blockIdx.x;      // scale
    const int bh = blockIdx.y;      // b*4+h
    float* Sp = S + (long)bh*240*240 + (long)roff[s]*240;  // contiguous [d,240] block
    const int d = dsz[s];
    const int cnt = d * 240;
    const float alpha = 0.0322748612f;  // 1/sqrt(960); folded here so eps semantics match ref
    const int tid = threadIdx.x;

    // pass 1: mean / biased var
    float lsum = 0.f, lsq = 0.f;
    for (int i = tid; i < cnt; i += 256) {
        float x = Sp[i] * alpha;
        lsum += x; lsq += x*x;
    }
    __shared__ float r1[256], r2[256];
    r1[tid] = lsum; r2[tid] = lsq;
    __syncthreads();
    for (int o = 128; o; o >>= 1) {
        if (tid < o) { r1[tid] += r1[tid+o]; r2[tid] += r2[tid+o]; }
        __syncthreads();
    }
    const float mean = r1[0] / cnt;
    const float var  = r2[0] / cnt - mean*mean;
    const float rstd = rsqrtf(var + 1e-5f);

    // pass 2: softmax per row over 240 cols (one warp per row)
    const int w = tid >> 5, lane = tid & 31;
    for (int r = w; r < d; r += 8) {
        float zv[8];
        float mx = -1e30f;
        #pragma unroll
        for (int j = 0; j < 8; j++) {
            int c = lane + 32*j;
            if (c < 240) {
                float x = (Sp[r*240 + c]*alpha - mean) * rstd;
                zv[j] = x; mx = fmaxf(mx, x);
            } else zv[j] = -1e30f;
        }
        for (int o = 16; o; o >>= 1) mx = fmaxf(mx, __shfl_xor_sync(0xffffffffu, mx, o));
        float ssum = 0.f;
        #pragma unroll
        for (int j = 0; j < 8; j++) {
            int c = lane + 32*j;
            if (c < 240) { float e = __expf(zv[j] - mx); zv[j] = e; ssum += e; }
        }
        for (int o = 16; o; o >>= 1) ssum += __shfl_xor_sync(0xffffffffu, ssum, o);
        float inv = __frcp_rn(ssum);
        #pragma unroll
        for (int j = 0; j < 8; j++) {
            int c = lane + 32*j;
            if (c < 240) Sp[r*240 + c] = zv[j] * inv;
        }
    }
}

// ---------------- launch ----------------
extern "C" void kernel_launch(void* const* d_in, const int* in_sizes, int n_in,
                              void* d_out, int out_size)
{
    const float* emb[4]  = {(const float*)d_in[0], (const float*)d_in[1],
                            (const float*)d_in[2], (const float*)d_in[3]};
    const float* emb_all = (const float*)d_in[4];
    const float* Wq[4]   = {(const float*)d_in[5], (const float*)d_in[6],
                            (const float*)d_in[7], (const float*)d_in[8]};
    const float* Wk      = (const float*)d_in[9];
    const float* Wv      = (const float*)d_in[10];
    const float* Wo[4]   = {(const float*)d_in[11], (const float*)d_in[12],
                            (const float*)d_in[13], (const float*)d_in[14]};
    float* out = (float*)d_out;

    float *Kh, *Vh, *Q, *S, *ctx;
    cudaGetSymbolAddress((void**)&Kh,  g_Kh);
    cudaGetSymbolAddress((void**)&Vh,  g_Vh);
    cudaGetSymbolAddress((void**)&Q,   g_Q);
    cudaGetSymbolAddress((void**)&S,   g_S);
    cudaGetSymbolAddress((void**)&ctx, g_ctx);

    const int  CHs[4]  = {64, 128, 256, 512};
    const int  qoff[4] = {0, 16, 48, 112};
    const long boff[4] = {0, 16384L*64, 16384L*192, 16384L*448};

    const long st = 4L*1024*240;   // per-b stride of [B,H,N,240]
    const long sh = 1024L*240;     // per-h stride
    const long Sb = 4L*240*240;    // per-b stride of scores
    const long Sh = 240L*240;

    // 1) K/V projections (gathered A from emb_all): per (b,h) [1024,240]x[240,240]^T
    gemm_k<false, true, 0><<<dim3(16, 4, 64), 256>>>(
        emb_all, 1024L*960, 0, 960,  Wk, 0, 0, 240,  Kh, st, sh, 240,  1024, 240, 240);
    gemm_k<false, true, 0><<<dim3(16, 4, 64), 256>>>(
        emb_all, 1024L*960, 0, 960,  Wv, 0, 0, 240,  Vh, st, sh, 240,  1024, 240, 240);

    // 2) Q projections (4 scales) into packed g_Q columns
    for (int sc = 0; sc < 4; sc++) {
        int c = CHs[sc], d = c / 4;
        gemm_k<false, false, 0><<<dim3(16, (d + 63)/64, 64), 256>>>(
            emb[sc], 1024L*c, d, c,  Wq[sc], 0, (long)d*d, d,
            Q + qoff[sc], st, sh, 240,  1024, d, d);
    }

    // 3) scores = Q^T K over N=1024 (TN): per (b,h) [240,240]
    gemm_k<true, false, 0><<<dim3(4, 4, 64), 256>>>(
        Q, st, sh, 240,  Kh, st, sh, 240,  S, Sb, Sh, 240,  240, 240, 1024);

    // 4) instance-norm + softmax (in place)
    norm_softmax_k<<<dim3(4, 64), 256>>>(S);

    // 5) ctx = probs @ V^T, scattered into [B,N,c] per-scale layout
    gemm_k<false, false, 1><<<dim3(4, 16, 64), 256>>>(
        S, Sb, Sh, 240,  Vh, st, sh, 240,  ctx, 0, 0, 0,  240, 1024, 240);

    // 6) output projections per scale: [16384,c] x [c,c]^T
    for (int sc = 0; sc < 4; sc++) {
        int c = CHs[sc];
        gemm_k<false, false, 0><<<dim3(256, c/64, 1), 256>>>(
            ctx + boff[sc], 0, 0, c,  Wo[sc], 0, 0, c,
            out + boff[sc], 0, 0, c,  16384, c, c);
    }
}

// round 2
// speedup vs baseline: 2.2210x; 2.2210x over previous
#include <cuda_runtime.h>
#include <cstdint>

// ---------------- scratch (static device globals; no allocs allowed) ----------------
__device__ float g_Kh [16*4*1024*240];   // [B,H,N,240]
__device__ float g_Vh [16*4*1024*240];   // [B,H,N,240]
__device__ float g_Q  [16*4*1024*240];   // [B,H,N,240] (4 scales packed at col offsets 0/16/48/112)
__device__ float g_S  [16*4*240*240];    // [B,H,240,240] scores -> probs (in place)
__device__ float g_ctx[16*1024*960];     // per-scale ctx in [B,N,c] layout, concatenated

// head-channel regrouping of emb_all: head h, local dim d -> emb_all channel.
// NOTE: run boundaries (16,48,112) are multiples of 16, so within any 16-wide
// k-tile head_map(k0+e,h) == head_map(k0,h)+e.
__device__ __forceinline__ int head_map(int d, int h) {
    if (d < 16)  return h*16  + d;
    if (d < 48)  return 64  + h*32  + (d-16);
    if (d < 112) return 192 + h*64  + (d-48);
    return 448 + h*128 + (d-112);
}

__device__ __forceinline__ uint32_t f2tf(float x) {
    uint32_t r;
    asm("cvt.rna.tf32.f32 %0, %1;" : "=r"(r) : "f"(x));
    return r;
}

// ---------------- tf32 tensor-core tiled GEMM ----------------
// NT (TN=false): C[m,n] = sum_k A[m*lda+k] * B[n*ldb+k]
// TN (TN=true) : C[m,n] = sum_k A[k*lda+m] * B[k*ldb+n]
// GATHER: A column index remapped via head_map (K/V projection from emb_all)
// CMODE 0: plain store; CMODE 1: ctx scatter (transpose(0,3,2,1) interleave)
// Block tile 128x128, K-tile 16. 8 warps; warp tile 64(m) x 32(n).
// mma.sync.m16n8k8 tf32. Requires K % 16 == 0 (true for all shapes here).
template<bool TN, bool GATHER, int CMODE>
__global__ __launch_bounds__(256, 2) void mma_gemm(
    const float* __restrict__ A, long a_bs, long a_hs, int lda,
    const float* __restrict__ B, long b_bs, long b_hs, int ldb,
    float* __restrict__ C, long c_bs, long c_hs, int ldc,
    int M, int Nn, int Kk)
{
    __shared__ uint32_t As[16][136];
    __shared__ uint32_t Bs[16][136];

    const int z = blockIdx.z;
    const int b = z >> 2, h = z & 3;
    A += (long)b*a_bs + (long)h*a_hs;
    B += (long)b*b_bs + (long)h*b_hs;
    if (CMODE == 0) C += (long)b*c_bs + (long)h*c_hs;

    const int tid  = threadIdx.x;
    const int warp = tid >> 5, lane = tid & 31;
    const int grp  = lane >> 2, qid = lane & 3;
    const int wm0  = (warp & 1) * 64;
    const int wn0  = (warp >> 1) * 32;
    const int m0 = blockIdx.x * 128, n0 = blockIdx.y * 128;

    float acc[4][4][4];
    #pragma unroll
    for (int i = 0; i < 4; i++)
        #pragma unroll
        for (int j = 0; j < 4; j++)
            #pragma unroll
            for (int r = 0; r < 4; r++) acc[i][j][r] = 0.f;

    for (int k0 = 0; k0 < Kk; k0 += 16) {
        if (!TN) {
            // A/B row-major [rows, K]; load 8 k-contiguous floats per thread,
            // transpose into k-major smem as tf32.
            const int row = tid >> 1, kq = (tid & 1) * 8;
            {
                const int m = m0 + row;
                float4 v0 = make_float4(0.f,0.f,0.f,0.f), v1 = v0;
                if (m < M) {
                    const float* p = A + (long)m*lda
                                   + (GATHER ? head_map(k0, h) + kq : k0 + kq);
                    v0 = *(const float4*)p;
                    v1 = *(const float4*)(p + 4);
                }
                As[kq+0][row] = f2tf(v0.x); As[kq+1][row] = f2tf(v0.y);
                As[kq+2][row] = f2tf(v0.z); As[kq+3][row] = f2tf(v0.w);
                As[kq+4][row] = f2tf(v1.x); As[kq+5][row] = f2tf(v1.y);
                As[kq+6][row] = f2tf(v1.z); As[kq+7][row] = f2tf(v1.w);
            }
            {
                const int n = n0 + row;
                float4 v0 = make_float4(0.f,0.f,0.f,0.f), v1 = v0;
                if (n < Nn) {
                    const float* p = B + (long)n*ldb + k0 + kq;
                    v0 = *(const float4*)p;
                    v1 = *(const float4*)(p + 4);
                }
                Bs[kq+0][row] = f2tf(v0.x); Bs[kq+1][row] = f2tf(v0.y);
                Bs[kq+2][row] = f2tf(v0.z); Bs[kq+3][row] = f2tf(v0.w);
                Bs[kq+4][row] = f2tf(v1.x); Bs[kq+5][row] = f2tf(v1.y);
                Bs[kq+6][row] = f2tf(v1.z); Bs[kq+7][row] = f2tf(v1.w);
            }
        } else {
            // A/B stored [K, cols]; already k-major, direct tiles.
            const int kr = tid >> 4, q = (tid & 15) * 8;
            {
                float4 v0 = make_float4(0.f,0.f,0.f,0.f), v1 = v0;
                const float* p = A + (long)(k0+kr)*lda + m0 + q;
                if (m0 + q     < M) v0 = *(const float4*)p;
                if (m0 + q + 4 < M) v1 = *(const float4*)(p + 4);
                As[kr][q+0] = f2tf(v0.x); As[kr][q+1] = f2tf(v0.y);
                As[kr][q+2] = f2tf(v0.z); As[kr][q+3] = f2tf(v0.w);
                As[kr][q+4] = f2tf(v1.x); As[kr][q+5] = f2tf(v1.y);
                As[kr][q+6] = f2tf(v1.z); As[kr][q+7] = f2tf(v1.w);
            }
            {
                float4 v0 = make_float4(0.f,0.f,0.f,0.f), v1 = v0;
                const float* p = B + (long)(k0+kr)*ldb + n0 + q;
                if (n0 + q     < Nn) v0 = *(const float4*)p;
                if (n0 + q + 4 < Nn) v1 = *(const float4*)(p + 4);
                Bs[kr][q+0] = f2tf(v0.x); Bs[kr][q+1] = f2tf(v0.y);
                Bs[kr][q+2] = f2tf(v0.z); Bs[kr][q+3] = f2tf(v0.w);
                Bs[kr][q+4] = f2tf(v1.x); Bs[kr][q+5] = f2tf(v1.y);
                Bs[kr][q+6] = f2tf(v1.z); Bs[kr][q+7] = f2tf(v1.w);
            }
        }
        __syncthreads();

        #pragma unroll
        for (int ks = 0; ks < 2; ks++) {
            const int kb = ks * 8;
            uint32_t a[4][4], bf[4][2];
            #pragma unroll
            for (int i = 0; i < 4; i++) {
                const int mr = wm0 + i*16 + grp;
                a[i][0] = As[kb+qid  ][mr];
                a[i][1] = As[kb+qid  ][mr+8];
                a[i][2] = As[kb+qid+4][mr];
                a[i][3] = As[kb+qid+4][mr+8];
            }
            #pragma unroll
            for (int j = 0; j < 4; j++) {
                const int nc = wn0 + j*8 + grp;
                bf[j][0] = Bs[kb+qid  ][nc];
                bf[j][1] = Bs[kb+qid+4][nc];
            }
            #pragma unroll
            for (int i = 0; i < 4; i++)
                #pragma unroll
                for (int j = 0; j < 4; j++) {
                    asm volatile(
                        "mma.sync.aligned.m16n8k8.row.col.f32.tf32.tf32.f32 "
                        "{%0,%1,%2,%3}, {%4,%5,%6,%7}, {%8,%9}, {%0,%1,%2,%3};\n"
                        : "+f"(acc[i][j][0]), "+f"(acc[i][j][1]),
                          "+f"(acc[i][j][2]), "+f"(acc[i][j][3])
                        : "r"(a[i][0]), "r"(a[i][1]), "r"(a[i][2]), "r"(a[i][3]),
                          "r"(bf[j][0]), "r"(bf[j][1]));
                }
        }
        __syncthreads();
    }

    // epilogue
    #pragma unroll
    for (int i = 0; i < 4; i++) {
        #pragma unroll
        for (int j = 0; j < 4; j++) {
            const int mA = m0 + wm0 + i*16 + grp;
            const int nA = n0 + wn0 + j*8 + 2*qid;
            #pragma unroll
            for (int half = 0; half < 2; half++) {
                const int m = mA + half*8;
                const float c0 = acc[i][j][half*2+0];
                const float c1 = acc[i][j][half*2+1];
                if (CMODE == 0) {
                    if (m < M && nA < Nn) {   // Nn even, nA even -> pair in-bounds
                        float2 v = make_float2(c0, c1);
                        *(float2*)&C[(long)m*ldc + nA] = v;
                    }
                } else {
                    if (m < M && nA < Nn) {
                        int s, doff;
                        if      (m < 16)  { s = 0; doff = m; }
                        else if (m < 48)  { s = 1; doff = m - 16; }
                        else if (m < 112) { s = 2; doff = m - 48; }
                        else              { s = 3; doff = m - 112; }
                        const long ctxoff[4] = {0, 16384L*64, 16384L*192, 16384L*448};
                        const int  chc[4]    = {64, 128, 256, 512};
                        long base = ctxoff[s] + (long)doff*4 + h;
                        C[base + ((long)(b*1024 + nA  ))*chc[s]] = c0;
                        C[base + ((long)(b*1024 + nA+1))*chc[s]] = c1;
                    }
                }
            }
        }
    }
}

// ---------------- instance-norm (per b,h,scale over [d,240]) + row softmax ----------------
__global__ __launch_bounds__(256) void norm_softmax_k(float* __restrict__ S)
{
    const int roff[4] = {0, 16, 48, 112};
    const int dsz[4]  = {16, 32, 64, 128};
    const int s  = blockIdx.x;      // scale
    const int bh = blockIdx.y;      // b*4+h
    float* Sp = S + (long)bh*240*240 + (long)roff[s]*240;  // contiguous [d,240] block
    const int d = dsz[s];
    const int cnt = d * 240;
    const float alpha = 0.0322748612f;  // 1/sqrt(960)
    const int tid = threadIdx.x;

    float lsum = 0.f, lsq = 0.f;
    for (int i = tid; i < cnt; i += 256) {
        float x = Sp[i] * alpha;
        lsum += x; lsq += x*x;
    }
    __shared__ float r1[256], r2[256];
    r1[tid] = lsum; r2[tid] = lsq;
    __syncthreads();
    for (int o = 128; o; o >>= 1) {
        if (tid < o) { r1[tid] += r1[tid+o]; r2[tid] += r2[tid+o]; }
        __syncthreads();
    }
    const float mean = r1[0] / cnt;
    const float var  = r2[0] / cnt - mean*mean;
    const float rstd = rsqrtf(var + 1e-5f);

    const int w = tid >> 5, lane = tid & 31;
    for (int r = w; r < d; r += 8) {
        float zv[8];
        float mx = -1e30f;
        #pragma unroll
        for (int j = 0; j < 8; j++) {
            int c = lane + 32*j;
            if (c < 240) {
                float x = (Sp[r*240 + c]*alpha - mean) * rstd;
                zv[j] = x; mx = fmaxf(mx, x);
            } else zv[j] = -1e30f;
        }
        for (int o = 16; o; o >>= 1) mx = fmaxf(mx, __shfl_xor_sync(0xffffffffu, mx, o));
        float ssum = 0.f;
        #pragma unroll
        for (int j = 0; j < 8; j++) {
            int c = lane + 32*j;
            if (c < 240) { float e = __expf(zv[j] - mx); zv[j] = e; ssum += e; }
        }
        for (int o = 16; o; o >>= 1) ssum += __shfl_xor_sync(0xffffffffu, ssum, o);
        float inv = __frcp_rn(ssum);
        #pragma unroll
        for (int j = 0; j < 8; j++) {
            int c = lane + 32*j;
            if (c < 240) Sp[r*240 + c] = zv[j] * inv;
        }
    }
}

// ---------------- launch ----------------
extern "C" void kernel_launch(void* const* d_in, const int* in_sizes, int n_in,
                              void* d_out, int out_size)
{
    const float* emb[4]  = {(const float*)d_in[0], (const float*)d_in[1],
                            (const float*)d_in[2], (const float*)d_in[3]};
    const float* emb_all = (const float*)d_in[4];
    const float* Wq[4]   = {(const float*)d_in[5], (const float*)d_in[6],
                            (const float*)d_in[7], (const float*)d_in[8]};
    const float* Wk      = (const float*)d_in[9];
    const float* Wv      = (const float*)d_in[10];
    const float* Wo[4]   = {(const float*)d_in[11], (const float*)d_in[12],
                            (const float*)d_in[13], (const float*)d_in[14]};
    float* out = (float*)d_out;

    float *Kh, *Vh, *Q, *S, *ctx;
    cudaGetSymbolAddress((void**)&Kh,  g_Kh);
    cudaGetSymbolAddress((void**)&Vh,  g_Vh);
    cudaGetSymbolAddress((void**)&Q,   g_Q);
    cudaGetSymbolAddress((void**)&S,   g_S);
    cudaGetSymbolAddress((void**)&ctx, g_ctx);

    const int  CHs[4]  = {64, 128, 256, 512};
    const int  qoff[4] = {0, 16, 48, 112};
    const long boff[4] = {0, 16384L*64, 16384L*192, 16384L*448};

    const long st = 4L*1024*240;   // per-b stride of [B,H,N,240]
    const long sh = 1024L*240;     // per-h stride
    const long Sb = 4L*240*240;
    const long Sh = 240L*240;

    // 1) K/V projections (gathered A from emb_all): per (b,h) [1024,240]x[240,240]^T
    mma_gemm<false, true, 0><<<dim3(8, 2, 64), 256>>>(
        emb_all, 1024L*960, 0, 960,  Wk, 0, 0, 240,  Kh, st, sh, 240,  1024, 240, 240);
    mma_gemm<false, true, 0><<<dim3(8, 2, 64), 256>>>(
        emb_all, 1024L*960, 0, 960,  Wv, 0, 0, 240,  Vh, st, sh, 240,  1024, 240, 240);

    // 2) Q projections (4 scales) into packed g_Q columns
    for (int sc = 0; sc < 4; sc++) {
        int c = CHs[sc], d = c / 4;
        mma_gemm<false, false, 0><<<dim3(8, 1, 64), 256>>>(
            emb[sc], 1024L*c, d, c,  Wq[sc], 0, (long)d*d, d,
            Q + qoff[sc], st, sh, 240,  1024, d, d);
    }

    // 3) scores = Q^T K over N=1024 (TN): per (b,h) [240,240]
    mma_gemm<true, false, 0><<<dim3(2, 2, 64), 256>>>(
        Q, st, sh, 240,  Kh, st, sh, 240,  S, Sb, Sh, 240,  240, 240, 1024);

    // 4) instance-norm + softmax (in place)
    norm_softmax_k<<<dim3(4, 64), 256>>>(S);

    // 5) ctx = probs @ V^T, scattered into [B,N,c] per-scale layout
    mma_gemm<false, false, 1><<<dim3(2, 8, 64), 256>>>(
        S, Sb, Sh, 240,  Vh, st, sh, 240,  ctx, 0, 0, 0,  240, 1024, 240);

    // 6) output projections per scale: [16384,c] x [c,c]^T
    for (int sc = 0; sc < 4; sc++) {
        int c = CHs[sc];
        int nb = c / 128; if (nb < 1) nb = 1;
        mma_gemm<false, false, 0><<<dim3(128, nb, 1), 256>>>(
            ctx + boff[sc], 0, 0, c,  Wo[sc], 0, 0, c,
            out + boff[sc], 0, 0, c,  16384, c, c);
    }
}